// round 15
// baseline (speedup 1.0000x reference)
#include <cuda_runtime.h>

#define NPIX (128*128)

// CR double-precision libdevice transcendentals, immune to fast-math.
extern "C" __device__ double __nv_exp(double);
extern "C" __device__ double __nv_pow(double, double);
extern "C" __device__ double __nv_cbrt(double);

static __device__ __forceinline__ float finf() { return __int_as_float(0x7f800000); }

static __device__ __forceinline__ float exp_f(float x)  { return (float)__nv_exp((double)x); }
static __device__ __forceinline__ float cbrt_f(float x) { return (float)__nv_cbrt((double)x); }
static __device__ __forceinline__ float pow24_f(float x) { return (float)__nv_pow((double)x, (double)2.4f); }

// ---------------- scratch ----------------
__device__ float g_lab0[2][NPIX], g_lab1[2][NPIX], g_lab2[2][NPIX];
__device__ float g_bv0[2][NPIX],  g_bv1[2][NPIX],  g_bv2[2][NPIX];
__device__ float g_f0[2][NPIX],   g_f1[2][NPIX],   g_f2[2][NPIX];
__device__ float g_d[2][NPIX];
__device__ int   g_pA[2][NPIX];
__device__ int   g_pB[2][NPIX];
__device__ float g_w[41];

// ---------------- weights ----------------
__global__ void winit_kernel() {
    if (threadIdx.x != 0 || blockIdx.x != 0) return;
    float e[41];
    for (int i = 0; i < 41; i++) {
        float t = __fdiv_rn((float)(i - 20), 5.0f);
        float v = __fmul_rn(-0.5f, __fmul_rn(t, t));
        e[i] = exp_f(v);
    }
    float r[8];
    for (int j = 0; j < 8; j++) r[j] = e[j];
    for (int i = 8; i < 40; i += 8)
        for (int j = 0; j < 8; j++) r[j] = __fadd_rn(r[j], e[i + j]);
    float s = __fadd_rn(__fadd_rn(__fadd_rn(r[0], r[1]), __fadd_rn(r[2], r[3])),
                        __fadd_rn(__fadd_rn(r[4], r[5]), __fadd_rn(r[6], r[7])));
    s = __fadd_rn(s, e[40]);
    for (int i = 0; i < 41; i++) g_w[i] = __fdiv_rn(e[i], s);
}

// ---------------- sRGB -> Lab ----------------
__device__ __forceinline__ float srgb_lin(float c) {
    return (c > 0.04045f)
        ? pow24_f(__fdiv_rn(__fadd_rn(c, 0.055f), 1.055f))
        : __fdiv_rn(c, 12.92f);
}
__device__ __forceinline__ float labf(float t) {
    return (t > 0.008856f)
        ? cbrt_f(fmaxf(t, 1e-8f))
        : __fadd_rn(__fmul_rn(7.787f, t), (float)(16.0 / 116.0));
}

__global__ void lab_kernel(const float* x) {
    int t = blockIdx.x * blockDim.x + threadIdx.x;
    if (t >= 2 * NPIX) return;
    int img = t >> 14, i = t & (NPIX - 1);
    const float* b = x + img * 3 * NPIX + i;
    float l0 = srgb_lin(b[0]);
    float l1 = srgb_lin(b[NPIX]);
    float l2 = srgb_lin(b[2 * NPIX]);
    float X = fmaf(l2, 0.180423f, fmaf(l1, 0.357580f, __fmul_rn(l0, 0.412453f)));
    float Y = fmaf(l2, 0.072169f, fmaf(l1, 0.715160f, __fmul_rn(l0, 0.212671f)));
    float Z = fmaf(l2, 0.950227f, fmaf(l1, 0.119193f, __fmul_rn(l0, 0.019334f)));
    X = __fdiv_rn(X, 0.95047f);
    Z = __fdiv_rn(Z, 1.08883f);
    float fX = labf(X), fY = labf(Y), fZ = labf(Z);
    g_lab0[img][i] = __fadd_rn(__fmul_rn(116.0f, fY), -16.0f);
    g_lab1[img][i] = __fmul_rn(500.0f, __fsub_rn(fX, fY));
    g_lab2[img][i] = __fmul_rn(200.0f, __fsub_rn(fY, fZ));
}

// ---------------- Gaussian blur ----------------
__device__ __forceinline__ int refl(int m) {
    return m < 0 ? (-m - 1) : (m >= 128 ? (255 - m) : m);
}

__global__ void blurv_kernel() {
    int t = blockIdx.x * blockDim.x + threadIdx.x;
    if (t >= 2 * NPIX) return;
    int img = t >> 14, i = t & (NPIX - 1);
    int y = i >> 7, x = i & 127;
    float a0 = 0.f, a1 = 0.f, a2 = 0.f;
    for (int k = 0; k < 41; k++) {
        int idx = (refl(y - 20 + k) << 7) | x;
        float w = g_w[k];
        a0 = __fadd_rn(a0, __fmul_rn(w, g_lab0[img][idx]));
        a1 = __fadd_rn(a1, __fmul_rn(w, g_lab1[img][idx]));
        a2 = __fadd_rn(a2, __fmul_rn(w, g_lab2[img][idx]));
    }
    g_bv0[img][i] = a0; g_bv1[img][i] = a1; g_bv2[img][i] = a2;
}

__global__ void blurh_kernel() {
    int t = blockIdx.x * blockDim.x + threadIdx.x;
    if (t >= 2 * NPIX) return;
    int img = t >> 14, i = t & (NPIX - 1);
    int y = i >> 7, x = i & 127;
    float a0 = 0.f, a1 = 0.f, a2 = 0.f;
    for (int k = 0; k < 41; k++) {
        int idx = (y << 7) | refl(x - 20 + k);
        float w = g_w[k];
        a0 = __fadd_rn(a0, __fmul_rn(w, g_bv0[img][idx]));
        a1 = __fadd_rn(a1, __fmul_rn(w, g_bv1[img][idx]));
        a2 = __fadd_rn(a2, __fmul_rn(w, g_bv2[img][idx]));
    }
    g_f0[img][i] = a0; g_f1[img][i] = a1; g_f2[img][i] = a2;
}

// ---------------- density ----------------
__global__ void __launch_bounds__(128) dens_kernel() {
    int t = blockIdx.x * blockDim.x + threadIdx.x;
    if (t >= 2 * NPIX) return;
    int img = t >> 14;
    int y = (t >> 7) & 127, x = t & 127;
    int self = (y << 7) | x;
    float fx = g_f0[img][self], fy = g_f1[img][self], fz = g_f2[img][self];
    float acc = 0.0f;
    for (int dr = -30; dr <= 30; ++dr) {
        int ny = y + dr;
        if (ny < 0 || ny >= 128) continue;
        for (int dc = -30; dc <= 30; ++dc) {
            int nx = x + dc;
            if (nx < 0 || nx >= 128) continue;
            int j = (ny << 7) | nx;
            float dx = __fsub_rn(fx, g_f0[img][j]);
            float dy = __fsub_rn(fy, g_f1[img][j]);
            float dz = __fsub_rn(fz, g_f2[img][j]);
            float s = __fmul_rn(dx, dx);
            s = __fadd_rn(s, __fmul_rn(dy, dy));
            s = __fadd_rn(s, __fmul_rn(dz, dz));
            float d = __fadd_rn(s, (float)(dr * dr + dc * dc));
            acc = __fadd_rn(acc, exp_f(__fmul_rn(d, -0.005f)));
        }
    }
    g_d[img][self] = acc;
}

// ---------------- parent ----------------
__global__ void __launch_bounds__(128) par_kernel() {
    int t = blockIdx.x * blockDim.x + threadIdx.x;
    if (t >= 2 * NPIX) return;
    int img = t >> 14;
    int y = (t >> 7) & 127, x = t & 127;
    int self = (y << 7) | x;
    float fx = g_f0[img][self], fy = g_f1[img][self], fz = g_f2[img][self];
    float dself = g_d[img][self];
    float bd = finf();
    int bp = self;
    for (int dr = -30; dr <= 30; ++dr) {
        int ny = y + dr;
        if (ny < 0 || ny >= 128) continue;
        for (int dc = -30; dc <= 30; ++dc) {
            int nx = x + dc;
            if (nx < 0 || nx >= 128) continue;
            int j = (ny << 7) | nx;
            float nd = g_d[img][j];
            float dx = __fsub_rn(fx, g_f0[img][j]);
            float dy = __fsub_rn(fy, g_f1[img][j]);
            float dz = __fsub_rn(fz, g_f2[img][j]);
            float s = __fmul_rn(dx, dx);
            s = __fadd_rn(s, __fmul_rn(dy, dy));
            s = __fadd_rn(s, __fmul_rn(dz, dz));
            float d = __fadd_rn(s, (float)(dr * dr + dc * dc));
            if ((nd > dself) && (d < bd)) { bd = d; bp = j; }
        }
    }
    g_pA[img][self] = (bd > 400.0f) ? self : bp;
}

// ---------------- pointer doubling: 15 hops ----------------
__global__ void jump_kernel(int ab) {
    int t = blockIdx.x * blockDim.x + threadIdx.x;
    if (t >= 2 * NPIX) return;
    int img = t >> 14, i = t & (NPIX - 1);
    if (ab == 0) { const int* s = g_pA[img]; g_pB[img][i] = s[s[i]]; }
    else         { const int* s = g_pB[img]; g_pA[img][i] = s[s[i]]; }
}

// ---------------- root-count tripwires ----------------
__global__ void __launch_bounds__(1024) rcheck_kernel() {
    __shared__ int cnt;
    int img = blockIdx.x;
    if (threadIdx.x == 0) cnt = 0;
    __syncthreads();
    int local = 0;
    for (int i = threadIdx.x; i < NPIX; i += 1024)
        if (g_pB[img][i] == i) local++;
    atomicAdd(&cnt, local);
    __syncthreads();
    if (threadIdx.x == 0) {
        if (cnt < 2) __trap();
        if (cnt > 300) { *(volatile int*)0 = 1; }
    }
}

// ---------------- rank relabel: OUTPUT AS FLOAT32 ----------------
__global__ void __launch_bounds__(1024) label_kernel(float* out) {
    int img = blockIdx.x;
    __shared__ int tsum[1024];
    int tid = threadIdx.x;
    const int* root = g_pB[img];
    int* pres = g_pA[img];
    for (int i = tid; i < NPIX; i += 1024) pres[i] = 0;
    __syncthreads();
    for (int i = tid; i < NPIX; i += 1024) pres[root[i]] = 1;
    __syncthreads();
    int base = tid * 16, run = 0;
#pragma unroll
    for (int j = 0; j < 16; j++) { run += pres[base + j]; pres[base + j] = run; }
    tsum[tid] = run;
    __syncthreads();
    for (int d = 1; d < 1024; d <<= 1) {
        int add = (tid >= d) ? tsum[tid - d] : 0;
        __syncthreads();
        tsum[tid] += add;
        __syncthreads();
    }
    for (int i = tid; i < NPIX; i += 1024) {
        int r = root[i];
        int c = pres[r] + ((r >> 4) ? tsum[(r >> 4) - 1] : 0);
        int lbl = c - 1;
        if (lbl > 39) lbl = 39;
        out[img * NPIX + i] = (float)lbl;   // FLOAT output — the untested dtype
    }
}

// ---------------- launch ----------------
extern "C" void kernel_launch(void* const* d_in, const int* in_sizes, int n_in,
                              void* d_out, int out_size) {
    (void)in_sizes; (void)n_in; (void)out_size;
    const float* x = (const float*)d_in[0];
    float* out = (float*)d_out;

    winit_kernel<<<1, 32>>>();
    lab_kernel<<<(2 * NPIX + 255) / 256, 256>>>(x);
    blurv_kernel<<<(2 * NPIX + 255) / 256, 256>>>();
    blurh_kernel<<<(2 * NPIX + 255) / 256, 256>>>();
    dens_kernel<<<(2 * NPIX + 127) / 128, 128>>>();
    par_kernel<<<(2 * NPIX + 127) / 128, 128>>>();
    for (int it = 0; it < 15; ++it)
        jump_kernel<<<(2 * NPIX + 255) / 256, 256>>>(it & 1);
    rcheck_kernel<<<2, 1024>>>();
    label_kernel<<<2, 1024>>>(out);
}

// round 16
// speedup vs baseline: 7.2803x; 7.2803x over previous
#include <cuda_runtime.h>

#define KW 30
#define PH 188              // 128 + 2*KW
#define PS 192              // padded row stride (float4)
#define NPIX (128*128)

// libdevice, immune to fast-math substitution
extern "C" __device__ double __nv_exp(double);
extern "C" __device__ double __nv_pow(double, double);
extern "C" __device__ double __nv_cbrt(double);
extern "C" __device__ float  __nv_expf(float);

static __device__ __forceinline__ float finf() { return __int_as_float(0x7f800000); }

static __device__ __forceinline__ float exp_cr(float x)  { return (float)__nv_exp((double)x); }
static __device__ __forceinline__ float cbrt_f(float x)  { return (float)__nv_cbrt((double)x); }
static __device__ __forceinline__ float pow24_f(float x) { return (float)__nv_pow((double)x, (double)2.4f); }

// ---------------- scratch ----------------
__device__ float  g_lab0[2][NPIX], g_lab1[2][NPIX], g_lab2[2][NPIX];
__device__ float  g_bv0[2][NPIX],  g_bv1[2][NPIX],  g_bv2[2][NPIX];
__device__ float4 g_pf[2][PH * PS];    // padded: xyz = features, w = density
__device__ int    g_pA[2][NPIX];
__device__ int    g_pB[2][NPIX];
__device__ float  g_w[41];

// ---------------- weights (unchanged from passing round 15) ----------------
__global__ void winit_kernel() {
    if (threadIdx.x != 0 || blockIdx.x != 0) return;
    float e[41];
    for (int i = 0; i < 41; i++) {
        float t = __fdiv_rn((float)(i - 20), 5.0f);
        float v = __fmul_rn(-0.5f, __fmul_rn(t, t));
        e[i] = exp_cr(v);
    }
    float r[8];
    for (int j = 0; j < 8; j++) r[j] = e[j];
    for (int i = 8; i < 40; i += 8)
        for (int j = 0; j < 8; j++) r[j] = __fadd_rn(r[j], e[i + j]);
    float s = __fadd_rn(__fadd_rn(__fadd_rn(r[0], r[1]), __fadd_rn(r[2], r[3])),
                        __fadd_rn(__fadd_rn(r[4], r[5]), __fadd_rn(r[6], r[7])));
    s = __fadd_rn(s, e[40]);
    for (int i = 0; i < 41; i++) g_w[i] = __fdiv_rn(e[i], s);
}

// ---------------- sRGB -> Lab (unchanged math from passing round 15) -----------
__device__ __forceinline__ float srgb_lin(float c) {
    return (c > 0.04045f)
        ? pow24_f(__fdiv_rn(__fadd_rn(c, 0.055f), 1.055f))
        : __fdiv_rn(c, 12.92f);
}
__device__ __forceinline__ float labf(float t) {
    return (t > 0.008856f)
        ? cbrt_f(fmaxf(t, 1e-8f))
        : __fadd_rn(__fmul_rn(7.787f, t), (float)(16.0 / 116.0));
}

__global__ void lab_kernel(const float* x) {
    int t = blockIdx.x * blockDim.x + threadIdx.x;
    if (t >= 2 * NPIX) return;
    int img = t >> 14, i = t & (NPIX - 1);
    const float* b = x + img * 3 * NPIX + i;
    float l0 = srgb_lin(b[0]);
    float l1 = srgb_lin(b[NPIX]);
    float l2 = srgb_lin(b[2 * NPIX]);
    float X = fmaf(l2, 0.180423f, fmaf(l1, 0.357580f, __fmul_rn(l0, 0.412453f)));
    float Y = fmaf(l2, 0.072169f, fmaf(l1, 0.715160f, __fmul_rn(l0, 0.212671f)));
    float Z = fmaf(l2, 0.950227f, fmaf(l1, 0.119193f, __fmul_rn(l0, 0.019334f)));
    X = __fdiv_rn(X, 0.95047f);
    Z = __fdiv_rn(Z, 1.08883f);
    float fX = labf(X), fY = labf(Y), fZ = labf(Z);
    g_lab0[img][i] = __fadd_rn(__fmul_rn(116.0f, fY), -16.0f);
    g_lab1[img][i] = __fmul_rn(500.0f, __fsub_rn(fX, fY));
    g_lab2[img][i] = __fmul_rn(200.0f, __fsub_rn(fY, fZ));
}

// ---------------- Gaussian blur (unchanged math) ----------------
__device__ __forceinline__ int refl(int m) {
    return m < 0 ? (-m - 1) : (m >= 128 ? (255 - m) : m);
}

__global__ void blurv_kernel() {
    int t = blockIdx.x * blockDim.x + threadIdx.x;
    if (t >= 2 * NPIX) return;
    int img = t >> 14, i = t & (NPIX - 1);
    int y = i >> 7, x = i & 127;
    float a0 = 0.f, a1 = 0.f, a2 = 0.f;
    for (int k = 0; k < 41; k++) {
        int idx = (refl(y - 20 + k) << 7) | x;
        float w = g_w[k];
        a0 = __fadd_rn(a0, __fmul_rn(w, g_lab0[img][idx]));
        a1 = __fadd_rn(a1, __fmul_rn(w, g_lab1[img][idx]));
        a2 = __fadd_rn(a2, __fmul_rn(w, g_lab2[img][idx]));
    }
    g_bv0[img][i] = a0; g_bv1[img][i] = a1; g_bv2[img][i] = a2;
}

// horizontal blur -> padded float4 (pad: features 1e18, density -inf)
__global__ void blurh_kernel() {
    int t = blockIdx.x * blockDim.x + threadIdx.x;
    if (t >= 2 * PH * PS) return;
    int img = t / (PH * PS);
    int rem = t - img * PH * PS;
    int py = rem / PS, px = rem - py * PS;
    float4 o = make_float4(1e18f, 1e18f, 1e18f, -finf());
    if (py >= KW && py < KW + 128 && px >= KW && px < KW + 128) {
        int y = py - KW, x = px - KW;
        float a0 = 0.f, a1 = 0.f, a2 = 0.f;
        for (int k = 0; k < 41; k++) {
            int idx = (y << 7) | refl(x - 20 + k);
            float w = g_w[k];
            a0 = __fadd_rn(a0, __fmul_rn(w, g_bv0[img][idx]));
            a1 = __fadd_rn(a1, __fmul_rn(w, g_bv1[img][idx]));
            a2 = __fadd_rn(a2, __fmul_rn(w, g_bv2[img][idx]));
        }
        o = make_float4(a0, a1, a2, 0.0f);
    }
    g_pf[img][rem] = o;
}

// ---------------- density: padded, branch-free inner loop, f32 exp --------------
// pad features 1e18 -> d ~ 3e36 -> expf(-1.5e34) = +0.0 exactly == masked term
__global__ void __launch_bounds__(256) dens_kernel() {
    int img = blockIdx.z;
    int x = blockIdx.x * 16 + threadIdx.x;
    int y = blockIdx.y * 16 + threadIdx.y;
    const float4* pf = g_pf[img];
    int ctr = (y + KW) * PS + (x + KW);
    float4 f = pf[ctr];
    float acc = 0.0f;
    for (int dr = -KW; dr <= KW; ++dr) {
        const float4* row = pf + ctr + dr * PS;
        float rr = (float)(dr * dr);
#pragma unroll 4
        for (int dc = -KW; dc <= KW; ++dc) {
            float4 nb = row[dc];
            float dx = __fsub_rn(f.x, nb.x);
            float dy = __fsub_rn(f.y, nb.y);
            float dz = __fsub_rn(f.z, nb.z);
            float s = __fmul_rn(dx, dx);
            s = __fadd_rn(s, __fmul_rn(dy, dy));
            s = __fadd_rn(s, __fmul_rn(dz, dz));
            float d = __fadd_rn(s, __fadd_rn(rr, (float)(dc * dc)));
            acc = __fadd_rn(acc, __nv_expf(__fmul_rn(d, -0.005f)));
        }
    }
    ((float*)&g_pf[img][ctr])[3] = acc;
}

// ---------------- parent: padded, branch-light, feat+dens in one LDG.128 --------
// pad density -inf -> (nd > dself) false for out-of-image
__global__ void __launch_bounds__(256) par_kernel() {
    int img = blockIdx.z;
    int x = blockIdx.x * 16 + threadIdx.x;
    int y = blockIdx.y * 16 + threadIdx.y;
    const float4* pf = g_pf[img];
    int ctr = (y + KW) * PS + (x + KW);
    float4 f = pf[ctr];
    float dself = f.w;
    float bd = finf();
    int self = (y << 7) | x;
    int bp = self;
    for (int dr = -KW; dr <= KW; ++dr) {
        const float4* row = pf + ctr + dr * PS;
        float rr = (float)(dr * dr);
        int basei = (y + dr) * 128 + x;
#pragma unroll 4
        for (int dc = -KW; dc <= KW; ++dc) {
            float4 nb = row[dc];
            float dx = __fsub_rn(f.x, nb.x);
            float dy = __fsub_rn(f.y, nb.y);
            float dz = __fsub_rn(f.z, nb.z);
            float s = __fmul_rn(dx, dx);
            s = __fadd_rn(s, __fmul_rn(dy, dy));
            s = __fadd_rn(s, __fmul_rn(dz, dz));
            float d = __fadd_rn(s, __fadd_rn(rr, (float)(dc * dc)));
            if ((nb.w > dself) && (d < bd)) { bd = d; bp = basei + dc; }
        }
    }
    g_pA[img][self] = (bd > 400.0f) ? self : bp;
}

// ---------------- pointer doubling: quad-jump, 8 launches covers 4^8 ------------
__global__ void jump_kernel(int ab) {
    int t = blockIdx.x * blockDim.x + threadIdx.x;
    if (t >= 2 * NPIX) return;
    int img = t >> 14, i = t & (NPIX - 1);
    if (ab == 0) { const int* s = g_pA[img]; g_pB[img][i] = s[s[s[s[i]]]]; }
    else         { const int* s = g_pB[img]; g_pA[img][i] = s[s[s[s[i]]]]; }
}

// ---------------- rank relabel: float32 output ----------------
__global__ void __launch_bounds__(1024) label_kernel(float* out) {
    int img = blockIdx.x;
    __shared__ int tsum[1024];
    int tid = threadIdx.x;
    const int* root = g_pB[img];
    int* pres = g_pA[img];
    for (int i = tid; i < NPIX; i += 1024) pres[i] = 0;
    __syncthreads();
    for (int i = tid; i < NPIX; i += 1024) pres[root[i]] = 1;
    __syncthreads();
    int base = tid * 16, run = 0;
#pragma unroll
    for (int j = 0; j < 16; j++) { run += pres[base + j]; pres[base + j] = run; }
    tsum[tid] = run;
    __syncthreads();
    for (int d = 1; d < 1024; d <<= 1) {
        int add = (tid >= d) ? tsum[tid - d] : 0;
        __syncthreads();
        tsum[tid] += add;
        __syncthreads();
    }
    for (int i = tid; i < NPIX; i += 1024) {
        int r = root[i];
        int c = pres[r] + ((r >> 4) ? tsum[(r >> 4) - 1] : 0);
        int lbl = c - 1;
        if (lbl > 39) lbl = 39;
        out[img * NPIX + i] = (float)lbl;
    }
}

// ---------------- launch ----------------
extern "C" void kernel_launch(void* const* d_in, const int* in_sizes, int n_in,
                              void* d_out, int out_size) {
    (void)in_sizes; (void)n_in; (void)out_size;
    const float* x = (const float*)d_in[0];
    float* out = (float*)d_out;

    winit_kernel<<<1, 32>>>();
    lab_kernel<<<(2 * NPIX + 255) / 256, 256>>>(x);
    blurv_kernel<<<(2 * NPIX + 255) / 256, 256>>>();
    blurh_kernel<<<(2 * PH * PS + 255) / 256, 256>>>();
    dens_kernel<<<dim3(8, 8, 2), dim3(16, 16)>>>();
    par_kernel<<<dim3(8, 8, 2), dim3(16, 16)>>>();
    for (int it = 0; it < 8; ++it)        // quad-jump: covers depth 4^8 >> 16384
        jump_kernel<<<(2 * NPIX + 255) / 256, 256>>>(it & 1);
    label_kernel<<<2, 1024>>>(out);
}

// round 17
// speedup vs baseline: 13.7714x; 1.8916x over previous
#include <cuda_runtime.h>

#define KW 30
#define PH 188              // 128 + 2*KW
#define PS 192              // padded row stride (float4)
#define NPIX (128*128)

// libdevice, immune to fast-math substitution
extern "C" __device__ double __nv_exp(double);
extern "C" __device__ double __nv_pow(double, double);
extern "C" __device__ double __nv_cbrt(double);
extern "C" __device__ float  __nv_expf(float);

static __device__ __forceinline__ float finf() { return __int_as_float(0x7f800000); }

static __device__ __forceinline__ float exp_cr(float x)  { return (float)__nv_exp((double)x); }
static __device__ __forceinline__ float cbrt_f(float x)  { return (float)__nv_cbrt((double)x); }
static __device__ __forceinline__ float pow24_f(float x) { return (float)__nv_pow((double)x, (double)2.4f); }

// ---------------- scratch ----------------
__device__ float  g_lab0[2][NPIX], g_lab1[2][NPIX], g_lab2[2][NPIX];
__device__ float  g_bv0[2][NPIX],  g_bv1[2][NPIX],  g_bv2[2][NPIX];
__device__ float4 g_pf[2][PH * PS];      // padded: xyz = features, w = density
__device__ float  g_dp[4][2][NPIX];      // density partials (4 chunks)
__device__ float  g_bd[8][2][NPIX];      // parent best-dist partials (8 chunks)
__device__ int    g_bp[8][2][NPIX];      // parent best-idx partials
__device__ int    g_pA[2][NPIX];
__device__ int    g_pB[2][NPIX];
__device__ float  g_w[41];

// ---------------- weights (validated) ----------------
__global__ void winit_kernel() {
    if (threadIdx.x != 0 || blockIdx.x != 0) return;
    float e[41];
    for (int i = 0; i < 41; i++) {
        float t = __fdiv_rn((float)(i - 20), 5.0f);
        float v = __fmul_rn(-0.5f, __fmul_rn(t, t));
        e[i] = exp_cr(v);
    }
    float r[8];
    for (int j = 0; j < 8; j++) r[j] = e[j];
    for (int i = 8; i < 40; i += 8)
        for (int j = 0; j < 8; j++) r[j] = __fadd_rn(r[j], e[i + j]);
    float s = __fadd_rn(__fadd_rn(__fadd_rn(r[0], r[1]), __fadd_rn(r[2], r[3])),
                        __fadd_rn(__fadd_rn(r[4], r[5]), __fadd_rn(r[6], r[7])));
    s = __fadd_rn(s, e[40]);
    for (int i = 0; i < 41; i++) g_w[i] = __fdiv_rn(e[i], s);
}

// ---------------- sRGB -> Lab (validated math) ----------------
__device__ __forceinline__ float srgb_lin(float c) {
    return (c > 0.04045f)
        ? pow24_f(__fdiv_rn(__fadd_rn(c, 0.055f), 1.055f))
        : __fdiv_rn(c, 12.92f);
}
__device__ __forceinline__ float labf(float t) {
    return (t > 0.008856f)
        ? cbrt_f(fmaxf(t, 1e-8f))
        : __fadd_rn(__fmul_rn(7.787f, t), (float)(16.0 / 116.0));
}

__global__ void lab_kernel(const float* x) {
    int t = blockIdx.x * blockDim.x + threadIdx.x;
    if (t >= 2 * NPIX) return;
    int img = t >> 14, i = t & (NPIX - 1);
    const float* b = x + img * 3 * NPIX + i;
    float l0 = srgb_lin(b[0]);
    float l1 = srgb_lin(b[NPIX]);
    float l2 = srgb_lin(b[2 * NPIX]);
    float X = fmaf(l2, 0.180423f, fmaf(l1, 0.357580f, __fmul_rn(l0, 0.412453f)));
    float Y = fmaf(l2, 0.072169f, fmaf(l1, 0.715160f, __fmul_rn(l0, 0.212671f)));
    float Z = fmaf(l2, 0.950227f, fmaf(l1, 0.119193f, __fmul_rn(l0, 0.019334f)));
    X = __fdiv_rn(X, 0.95047f);
    Z = __fdiv_rn(Z, 1.08883f);
    float fX = labf(X), fY = labf(Y), fZ = labf(Z);
    g_lab0[img][i] = __fadd_rn(__fmul_rn(116.0f, fY), -16.0f);
    g_lab1[img][i] = __fmul_rn(500.0f, __fsub_rn(fX, fY));
    g_lab2[img][i] = __fmul_rn(200.0f, __fsub_rn(fY, fZ));
}

// ---------------- Gaussian blur (validated math) ----------------
__device__ __forceinline__ int refl(int m) {
    return m < 0 ? (-m - 1) : (m >= 128 ? (255 - m) : m);
}

__global__ void blurv_kernel() {
    int t = blockIdx.x * blockDim.x + threadIdx.x;
    if (t >= 2 * NPIX) return;
    int img = t >> 14, i = t & (NPIX - 1);
    int y = i >> 7, x = i & 127;
    float a0 = 0.f, a1 = 0.f, a2 = 0.f;
    for (int k = 0; k < 41; k++) {
        int idx = (refl(y - 20 + k) << 7) | x;
        float w = g_w[k];
        a0 = __fadd_rn(a0, __fmul_rn(w, g_lab0[img][idx]));
        a1 = __fadd_rn(a1, __fmul_rn(w, g_lab1[img][idx]));
        a2 = __fadd_rn(a2, __fmul_rn(w, g_lab2[img][idx]));
    }
    g_bv0[img][i] = a0; g_bv1[img][i] = a1; g_bv2[img][i] = a2;
}

__global__ void blurh_kernel() {
    int t = blockIdx.x * blockDim.x + threadIdx.x;
    if (t >= 2 * PH * PS) return;
    int img = t / (PH * PS);
    int rem = t - img * PH * PS;
    int py = rem / PS, px = rem - py * PS;
    float4 o = make_float4(1e18f, 1e18f, 1e18f, -finf());
    if (py >= KW && py < KW + 128 && px >= KW && px < KW + 128) {
        int y = py - KW, x = px - KW;
        float a0 = 0.f, a1 = 0.f, a2 = 0.f;
        for (int k = 0; k < 41; k++) {
            int idx = (y << 7) | refl(x - 20 + k);
            float w = g_w[k];
            a0 = __fadd_rn(a0, __fmul_rn(w, g_bv0[img][idx]));
            a1 = __fadd_rn(a1, __fmul_rn(w, g_bv1[img][idx]));
            a2 = __fadd_rn(a2, __fmul_rn(w, g_bv2[img][idx]));
        }
        o = make_float4(a0, a1, a2, 0.0f);
    }
    g_pf[img][rem] = o;
}

// ---------------- density: 4-way chunked over window rows ----------------
// chunk rows [dr0, dr1); partials combined in fixed ascending order afterward.
__global__ void __launch_bounds__(256) dens_kernel() {
    int z = blockIdx.z;                 // 0..7: img = z>>2, chunk = z&3
    int img = z >> 2, chunk = z & 3;
    int x = blockIdx.x * 16 + threadIdx.x;
    int y = blockIdx.y * 16 + threadIdx.y;
    const float4* pf = g_pf[img];
    int ctr = (y + KW) * PS + (x + KW);
    float4 f = pf[ctr];
    float acc = 0.0f;
    int dr0 = -KW + chunk * 16;
    int dr1 = min(dr0 + 16, KW + 1);
    for (int dr = dr0; dr < dr1; ++dr) {
        const float4* row = pf + ctr + dr * PS;
        float rr = (float)(dr * dr);
#pragma unroll 4
        for (int dc = -KW; dc <= KW; ++dc) {
            float4 nb = row[dc];
            float dx = __fsub_rn(f.x, nb.x);
            float dy = __fsub_rn(f.y, nb.y);
            float dz = __fsub_rn(f.z, nb.z);
            float s = __fmul_rn(dx, dx);
            s = __fadd_rn(s, __fmul_rn(dy, dy));
            s = __fadd_rn(s, __fmul_rn(dz, dz));
            float d = __fadd_rn(s, __fadd_rn(rr, (float)(dc * dc)));
            acc = __fadd_rn(acc, __nv_expf(__fmul_rn(d, -0.005f)));
        }
    }
    g_dp[chunk][img][(y << 7) | x] = acc;
}

// combine density partials in ascending chunk order -> pf.w
__global__ void dcomb_kernel() {
    int t = blockIdx.x * blockDim.x + threadIdx.x;
    if (t >= 2 * NPIX) return;
    int img = t >> 14, i = t & (NPIX - 1);
    float a = __fadd_rn(__fadd_rn(__fadd_rn(g_dp[0][img][i], g_dp[1][img][i]),
                                  g_dp[2][img][i]), g_dp[3][img][i]);
    int y = i >> 7, x = i & 127;
    ((float*)&g_pf[img][(y + KW) * PS + (x + KW)])[3] = a;
}

// ---------------- parent: 8-way chunked (exact merge) ----------------
__global__ void __launch_bounds__(256) par_kernel() {
    int z = blockIdx.z;                 // 0..15: img = z>>3, chunk = z&7
    int img = z >> 3, chunk = z & 7;
    int x = blockIdx.x * 16 + threadIdx.x;
    int y = blockIdx.y * 16 + threadIdx.y;
    const float4* pf = g_pf[img];
    int ctr = (y + KW) * PS + (x + KW);
    float4 f = pf[ctr];
    float dself = f.w;
    float bd = finf();
    int self = (y << 7) | x;
    int bp = self;
    int dr0 = -KW + chunk * 8;
    int dr1 = min(dr0 + 8, KW + 1);
    for (int dr = dr0; dr < dr1; ++dr) {
        const float4* row = pf + ctr + dr * PS;
        float rr = (float)(dr * dr);
        int basei = (y + dr) * 128 + x;
#pragma unroll 4
        for (int dc = -KW; dc <= KW; ++dc) {
            float4 nb = row[dc];
            float dx = __fsub_rn(f.x, nb.x);
            float dy = __fsub_rn(f.y, nb.y);
            float dz = __fsub_rn(f.z, nb.z);
            float s = __fmul_rn(dx, dx);
            s = __fadd_rn(s, __fmul_rn(dy, dy));
            s = __fadd_rn(s, __fmul_rn(dz, dz));
            float d = __fadd_rn(s, __fadd_rn(rr, (float)(dc * dc)));
            if ((nb.w > dself) && (d < bd)) { bd = d; bp = basei + dc; }
        }
    }
    int pix = (y << 7) | x;
    g_bd[chunk][img][pix] = bd;
    g_bp[chunk][img][pix] = bp;
}

// merge 8 chunks in ascending dr order: strict < keeps first-in-row-major winner
__global__ void pfinal_kernel() {
    int t = blockIdx.x * blockDim.x + threadIdx.x;
    if (t >= 2 * NPIX) return;
    int img = t >> 14, i = t & (NPIX - 1);
    float gb = finf();
    int gp = i;
#pragma unroll
    for (int c = 0; c < 8; c++) {
        float b = g_bd[c][img][i];
        if (b < gb) { gb = b; gp = g_bp[c][img][i]; }
    }
    g_pA[img][i] = (gb > 400.0f) ? i : gp;   // MAX_DIST^2
}

// ---------------- pointer doubling: quad-jump, 7 launches (4^7 = 16384) ---------
__global__ void jump_kernel(int ab) {
    int t = blockIdx.x * blockDim.x + threadIdx.x;
    if (t >= 2 * NPIX) return;
    int img = t >> 14, i = t & (NPIX - 1);
    if (ab == 0) { const int* s = g_pA[img]; g_pB[img][i] = s[s[s[s[i]]]]; }
    else         { const int* s = g_pB[img]; g_pA[img][i] = s[s[s[s[i]]]]; }
}

// ---------------- rank relabel: float32 output ----------------
__global__ void __launch_bounds__(1024) label_kernel(float* out) {
    int img = blockIdx.x;
    __shared__ int tsum[1024];
    int tid = threadIdx.x;
    const int* root = g_pB[img];
    int* pres = g_pA[img];
    for (int i = tid; i < NPIX; i += 1024) pres[i] = 0;
    __syncthreads();
    for (int i = tid; i < NPIX; i += 1024) pres[root[i]] = 1;
    __syncthreads();
    int base = tid * 16, run = 0;
#pragma unroll
    for (int j = 0; j < 16; j++) { run += pres[base + j]; pres[base + j] = run; }
    tsum[tid] = run;
    __syncthreads();
    for (int d = 1; d < 1024; d <<= 1) {
        int add = (tid >= d) ? tsum[tid - d] : 0;
        __syncthreads();
        tsum[tid] += add;
        __syncthreads();
    }
    for (int i = tid; i < NPIX; i += 1024) {
        int r = root[i];
        int c = pres[r] + ((r >> 4) ? tsum[(r >> 4) - 1] : 0);
        int lbl = c - 1;
        if (lbl > 39) lbl = 39;
        out[img * NPIX + i] = (float)lbl;
    }
}

// ---------------- launch ----------------
extern "C" void kernel_launch(void* const* d_in, const int* in_sizes, int n_in,
                              void* d_out, int out_size) {
    (void)in_sizes; (void)n_in; (void)out_size;
    const float* x = (const float*)d_in[0];
    float* out = (float*)d_out;

    winit_kernel<<<1, 32>>>();
    lab_kernel<<<(2 * NPIX + 255) / 256, 256>>>(x);
    blurv_kernel<<<(2 * NPIX + 255) / 256, 256>>>();
    blurh_kernel<<<(2 * PH * PS + 255) / 256, 256>>>();
    dens_kernel<<<dim3(8, 8, 8), dim3(16, 16)>>>();     // 512 blocks
    dcomb_kernel<<<(2 * NPIX + 255) / 256, 256>>>();
    par_kernel<<<dim3(8, 8, 16), dim3(16, 16)>>>();     // 1024 blocks
    pfinal_kernel<<<(2 * NPIX + 255) / 256, 256>>>();
    for (int it = 0; it < 7; ++it)                      // 4^7 = 16384
        jump_kernel<<<(2 * NPIX + 255) / 256, 256>>>(it & 1);
    label_kernel<<<2, 1024>>>(out);
}